// round 15
// baseline (speedup 1.0000x reference)
#include <cuda_runtime.h>
#include <cuda_bf16.h>
#include <math.h>

#define BB 16
#define QQ 50
#define GG 16
#define PP 64
#define NT 7
#define NSEG (PP - 1)

typedef unsigned long long u64;

// packed f32x2 helpers (only fma/mul/add exist for f32x2 on this toolchain)
#define F2PACK(d, lo, hi)  asm("mov.b64 %0, {%1,%2};" : "=l"(d) : "f"(lo), "f"(hi))
#define F2UNPACK(lo, hi, s) asm("mov.b64 {%0,%1}, %2;" : "=f"(lo), "=f"(hi) : "l"(s))
#define F2FMA(d, a, b, c)  asm("fma.rn.f32x2 %0, %1, %2, %3;" : "=l"(d) : "l"(a), "l"(b), "l"(c))
#define F2MUL(d, a, b)     asm("mul.rn.f32x2 %0, %1, %2;" : "=l"(d) : "l"(a), "l"(b))

// Scratch (device globals; no allocation allowed)
__device__ float g_curve[BB * QQ * GG];
__device__ float g_dir[BB * QQ * GG];
__device__ float g_cost[BB * QQ * GG];
__device__ float g_blk_pair[BB];
__device__ float g_blk_x[BB];
__device__ float g_blk_bce[BB];
__device__ int   g_done_counter;   // zero-init; last block resets each run

// ---------------------------------------------------------------------------
// Kernel A: cost matrix. One block per (b,q,g), 64 threads.
// Each WARP covers all 64 points (lane owns pts lane & lane+32); warps split
// the segment range with STATIC 32-iteration fully-unrolled loops:
//   warp 0: segs 0..31, warp 1: segs 31..62 (overlap at 31 harmless for min).
// ---------------------------------------------------------------------------
__global__ __launch_bounds__(PP) void cost_kernel(
    const float* __restrict__ pred_pts,
    const float* __restrict__ gt_pts,
    const float* __restrict__ gt_vis,
    const float* __restrict__ pred_exist)
{
    int blk = blockIdx.x;
    int g = blk % GG;
    int q = (blk / GG) % QQ;
    int b = blk / (GG * QQ);
    int t = threadIdx.x;   // 0..63
    int lane = t & 31, wid = t >> 5;

    __shared__ float2 sP[PP], sG[PP];
    __shared__ float  sV[PP];
    __shared__ ulonglong2 sS0[NSEG];  // (nx2, ny2)
    __shared__ ulonglong2 sS1[NSEG];  // (cr2, bx2)
    __shared__ ulonglong2 sS2[NSEG];  // (by2, cpa2)
    __shared__ u64        sS3[NSEG];  // ab22
    __shared__ float  sTdot[NSEG];
    __shared__ float  sMLo[2][PP], sMHi[2][PP];
    __shared__ float  sred[5][2];

    const float2* pp = (const float2*)(pred_pts + ((size_t)(b * QQ + q)) * PP * 2);
    const float2* gp = (const float2*)(gt_pts   + ((size_t)(b * GG + g)) * PP * 2);
    sP[t] = pp[t];
    sG[t] = gp[t];
    sV[t] = gt_vis[(size_t)(b * GG + g) * PP + t];
    __syncthreads();

    if (t < NSEG) {
        float2 aG = sG[t], bG = sG[t + 1];
        float abxg = bG.x - aG.x, abyg = bG.y - aG.y;
        float ab2g = abxg * abxg + abyg * abyg;
        float invg = 1.0f / fmaxf(ab2g, 1e-8f);
        float nxg = abxg * invg, nyg = abyg * invg;
        float crg = -(aG.x * abxg + aG.y * abyg) * invg;

        float2 aP = sP[t], bP = sP[t + 1];
        float abxp = bP.x - aP.x, abyp = bP.y - aP.y;
        float ab2p = abxp * abxp + abyp * abyp;
        float invp = 1.0f / fmaxf(ab2p, 1e-8f);
        float nxp = abxp * invp, nyp = abyp * invp;
        float crp = -(aP.x * abxp + aP.y * abyp) * invp;

        u64 nx2, ny2, cr2, bx2, by2, cpa2, ab22;
        F2PACK(nx2, nxg, nxp);
        F2PACK(ny2, nyg, nyp);
        F2PACK(cr2, crg, crp);
        F2PACK(bx2, -2.0f * aG.x, -2.0f * aP.x);
        F2PACK(by2, -2.0f * aG.y, -2.0f * aP.y);
        F2PACK(cpa2, aG.x * aG.x + aG.y * aG.y, aP.x * aP.x + aP.y * aP.y);
        F2PACK(ab22, ab2g, ab2p);
        sS0[t] = make_ulonglong2(nx2, ny2);
        sS1[t] = make_ulonglong2(cr2, bx2);
        sS2[t] = make_ulonglong2(by2, cpa2);
        sS3[t] = ab22;

        float itg = 1.0f / fmaxf(sqrtf(ab2g), 1e-6f);
        float itp = 1.0f / fmaxf(sqrtf(ab2p), 1e-6f);
        sTdot[t] = (abxp * abxg + abyp * abyg) * itg * itp;
    }
    __syncthreads();

    float2 Pa = sP[lane],      Ga = sG[lane];
    float2 Pb = sP[lane + 32], Gb = sG[lane + 32];
    u64 PxA, PyA, PxB, PyB, NEG2;
    F2PACK(PxA, Pa.x, Ga.x);
    F2PACK(PyA, Pa.y, Ga.y);
    F2PACK(PxB, Pb.x, Gb.x);
    F2PACK(PyB, Pb.y, Gb.y);
    F2PACK(NEG2, -2.0f, -2.0f);

    float mLoA = 3.0e38f, mHiA = 3.0e38f, mLoB = 3.0e38f, mHiB = 3.0e38f;
    int jBase = wid * 31;   // warp0: 0..31, warp1: 31..62 (overlap ok)

    #pragma unroll
    for (int jj = 0; jj < 32; jj++) {
        int j = jBase + jj;
        ulonglong2 A = sS0[j];
        ulonglong2 Bv = sS1[j];
        ulonglong2 Cv = sS2[j];
        u64 ab22 = sS3[j];

        {   // point slot A (pt = lane)
            u64 r2, pa2, t2, w2, z2, val2;
            F2FMA(r2, PyA, A.y, Bv.x);
            F2FMA(r2, PxA, A.x, r2);
            F2FMA(pa2, PyA, Cv.x, Cv.y);
            F2FMA(pa2, PxA, Bv.y, pa2);
            float rl, rh;
            F2UNPACK(rl, rh, r2);
            float tl = __saturatef(rl), th = __saturatef(rh);
            F2PACK(t2, tl, th);
            F2FMA(w2, r2, NEG2, t2);     // t - 2r
            F2MUL(z2, t2, w2);
            F2FMA(val2, z2, ab22, pa2);
            float vl, vh;
            F2UNPACK(vl, vh, val2);
            mLoA = fminf(mLoA, vl);
            mHiA = fminf(mHiA, vh);
        }
        {   // point slot B (pt = lane+32)
            u64 r2, pa2, t2, w2, z2, val2;
            F2FMA(r2, PyB, A.y, Bv.x);
            F2FMA(r2, PxB, A.x, r2);
            F2FMA(pa2, PyB, Cv.x, Cv.y);
            F2FMA(pa2, PxB, Bv.y, pa2);
            float rl, rh;
            F2UNPACK(rl, rh, r2);
            float tl = __saturatef(rl), th = __saturatef(rh);
            F2PACK(t2, tl, th);
            F2FMA(w2, r2, NEG2, t2);
            F2MUL(z2, t2, w2);
            F2FMA(val2, z2, ab22, pa2);
            float vl, vh;
            F2UNPACK(vl, vh, val2);
            mLoB = fminf(mLoB, vl);
            mHiB = fminf(mHiB, vh);
        }
    }
    sMLo[wid][lane] = mLoA; sMLo[wid][lane + 32] = mLoB;
    sMHi[wid][lane] = mHiA; sMHi[wid][lane + 32] = mHiB;
    __syncthreads();

    float mLo = fminf(sMLo[0][t], sMLo[1][t]);
    float mHi = fminf(sMHi[0][t], sMHi[1][t]);
    float2 myP = sP[t];
    float2 myG = sG[t];
    float myV = sV[t];

    float pp2 = myP.x * myP.x + myP.y * myP.y;
    float gg2 = myG.x * myG.x + myG.y * myG.y;
    float v0 = sqrtf(fmaxf(mLo + pp2, 1e-24f));          // dp2g
    float v1 = sqrtf(fmaxf(mHi + gg2, 1e-24f)) * myV;    // dg2p * vis
    float v2 = myV;
    float v3 = 0.0f, v4 = 0.0f;
    if (t < NSEG) {
        float sv_ = myV * sV[t + 1];
        v3 = (1.0f - sTdot[t]) * sv_;
        v4 = sv_;
    }

    #pragma unroll
    for (int off = 16; off > 0; off >>= 1) {
        v0 += __shfl_down_sync(0xffffffffu, v0, off);
        v1 += __shfl_down_sync(0xffffffffu, v1, off);
        v2 += __shfl_down_sync(0xffffffffu, v2, off);
        v3 += __shfl_down_sync(0xffffffffu, v3, off);
        v4 += __shfl_down_sync(0xffffffffu, v4, off);
    }
    if (lane == 0) {
        sred[0][wid] = v0; sred[1][wid] = v1; sred[2][wid] = v2;
        sred[3][wid] = v3; sred[4][wid] = v4;
    }
    __syncthreads();
    if (t == 0) {
        float s0 = sred[0][0] + sred[0][1];
        float s1 = sred[1][0] + sred[1][1];
        float s2 = sred[2][0] + sred[2][1];
        float s3 = sred[3][0] + sred[3][1];
        float s4 = sred[4][0] + sred[4][1];
        float visS = fmaxf(s2, 1.0f);
        float curve = 0.5f * (s0 * (1.0f / PP) + s1 / visS);
        float dir = s3 / fmaxf(s4, 1.0f);
        int idx = (b * QQ + q) * GG + g;
        g_curve[idx] = curve;
        g_dir[idx] = dir;
        float x = pred_exist[b * QQ + q];
        float sig = 1.0f / (1.0f + expf(-x));
        g_cost[idx] = curve + 0.35f * dir - 0.25f * sig;
    }
}

// ---------------------------------------------------------------------------
// Kernel B (R12-proven, byte-identical): ARR (exact duals) + exact Dijkstra
// with register caches and owner-lane shuffles + pair losses + final combine.
// ---------------------------------------------------------------------------
__device__ __forceinline__ unsigned okey(float f) {
    unsigned u = __float_as_uint(f);
    return (u & 0x80000000u) ? ~u : (u | 0x80000000u);
}
__device__ __forceinline__ float deokey(unsigned k) {
    unsigned u = (k & 0x80000000u) ? (k & 0x7FFFFFFFu) : ~k;
    return __uint_as_float(u);
}
__device__ __forceinline__ float smooth_l1(float x) {
    float ax = fabsf(x);
    return (ax < 1.0f) ? 0.5f * x * x : ax - 0.5f;
}

__global__ __launch_bounds__(128) void hungarian_pair_final_kernel(
    const float* __restrict__ pred_exist,
    const float* __restrict__ pred_pts,
    const float* __restrict__ pred_type,
    const float* __restrict__ gt_pts,
    const float* __restrict__ gt_vis,
    const int*   __restrict__ gt_type,
    float* __restrict__ out)
{
    int b = blockIdx.x;
    int tid = threadIdx.x;
    int lane = tid & 31, warp = tid >> 5;

    __shared__ float sC[GG][QQ];
    __shared__ int   sRow[QQ];
    __shared__ int   sway[QQ];
    __shared__ int   s_match[GG];
    __shared__ float s_wsum[4];
    __shared__ float s_xsum, s_bce;
    __shared__ int   s_last;
    __shared__ float s_red[128];

    for (int idx = tid; idx < GG * QQ; idx += 128) {
        int qq = idx >> 4, gg = idx & 15;
        sC[gg][qq] = g_cost[(b * QQ + qq) * GG + gg];
    }
    if (tid < QQ) sRow[tid] = -1;
    __syncthreads();

    if (warp == 0) {
        const float INF_F = 1e30f;
        int c0 = lane, c1 = lane + 32;
        bool have1 = (c1 < QQ);
        float v0 = 0.0f, v1 = 0.0f;   // column potentials, stay <= 0

        // ---- Augmenting Row Reduction (auction, eps=0, exact duals) ----
        unsigned todo = (1u << GG) - 1u;
        int steps = 0;
        while (todo && steps < 64) {
            steps++;
            int i = __ffs(todo) - 1;
            float a0 = sC[i][c0] - v0;
            float a1 = have1 ? (sC[i][c1] - v1) : INF_F;
            bool pick1 = a1 < a0;
            float lo = pick1 ? a1 : a0;
            float hi = pick1 ? a0 : a1;
            int locol = pick1 ? c1 : c0;
            unsigned klo = okey(lo);
            unsigned kmin = __reduce_min_sync(0xffffffffu, klo);   // exact min
            unsigned ball = __ballot_sync(0xffffffffu, klo == kmin);
            int jl = __ffs(ball) - 1;                              // winner lane
            int j1 = __shfl_sync(0xffffffffu, locol, jl);
            float m1 = deokey(kmin);                               // exact
            float lo2 = (lane == jl) ? hi : lo;
            float m2 = deokey(__reduce_min_sync(0xffffffffu, okey(lo2)));
            float dv = m2 - m1;                                    // >= 0 exact
            int kprev = sRow[j1];                                  // broadcast read
            __syncwarp();
            if (lane == jl) {
                if (j1 < 32) v0 -= dv; else v1 -= dv;
                sRow[j1] = i;
            }
            todo &= ~(1u << i);
            if (kprev >= 0) todo |= (1u << kprev);
            __syncwarp();
        }

        // ---- Exact Dijkstra (R6-proven) for any remaining rows ----
        unsigned pending = todo;
        while (pending) {
            int r0 = __ffs(pending) - 1;
            pending &= pending - 1;

            int rc0 = sRow[c0];
            int rc1 = have1 ? sRow[c1] : -1;
            float w0 = (rc0 >= 0) ? (sC[rc0][c0] - v0) : 0.0f;
            float w1 = (rc1 >= 0) ? (sC[rc1][c1] - v1) : 0.0f;
            float d0 = sC[r0][c0] - v0;
            float d1 = have1 ? (sC[r0][c1] - v1) : INF_F;
            sway[c0] = -1;
            if (have1) sway[c1] = -1;
            bool sc0 = false, sc1 = false;
            int jf; float D;

            while (true) {
                float cand0 = sc0 ? INF_F : d0;
                float cand1 = sc1 ? INF_F : d1;
                bool pick1 = cand1 < cand0;
                float bval = pick1 ? cand1 : cand0;
                unsigned bcol = pick1 ? (unsigned)c1 : (unsigned)c0;
                unsigned key = (okey(bval) & 0xFFFFFFC0u) | bcol;
                unsigned kmin = __reduce_min_sync(0xffffffffu, key);
                int js = (int)(kmin & 63u);
                int jl = js & 31;
                bool hiSlot = js >= 32;
                float sendD = hiSlot ? d1 : d0;
                float sendW = hiSlot ? w1 : w0;
                int   sendR = hiSlot ? rc1 : rc0;
                D         = __shfl_sync(0xffffffffu, sendD, jl);
                float Wjs = __shfl_sync(0xffffffffu, sendW, jl);
                int   rws = __shfl_sync(0xffffffffu, sendR, jl);
                if (lane == jl) { if (hiSlot) sc1 = true; else sc0 = true; }
                if (rws < 0) { jf = js; break; }
                float h = Wjs - D;   // = sC[rws][js] - v_js - D, no memory
                float a0 = sC[rws][c0] - v0 - h;
                if (!sc0 && a0 < d0) { d0 = a0; sway[c0] = js; }
                if (have1) {
                    float a1 = sC[rws][c1] - v1 - h;
                    if (!sc1 && a1 < d1) { d1 = a1; sway[c1] = js; }
                }
            }
            if (sc0) v0 += d0 - D;
            if (sc1) v1 += d1 - D;
            __syncwarp();
            if (lane == 0) {
                int cur = jf;
                while (true) {
                    int src = sway[cur];
                    if (src < 0) { sRow[cur] = r0; break; }
                    sRow[cur] = sRow[src];
                    cur = src;
                }
            }
            __syncwarp();
        }
        // extract matches
        {
            int r = sRow[c0];
            if (r >= 0) s_match[r] = c0;
            if (have1) { int r2 = sRow[c1]; if (r2 >= 0) s_match[r2] = c1; }
        }
        __syncwarp();
        float xs = (lane < GG) ? pred_exist[b * QQ + s_match[lane]] : 0.0f;
        #pragma unroll
        for (int off = 16; off > 0; off >>= 1) xs += __shfl_down_sync(0xffffffffu, xs, off);
        if (lane == 0) s_xsum = xs;
    } else if (warp == 1) {
        float acc = 0.0f;
        for (int q_ = lane; q_ < QQ; q_ += 32) {
            float x = pred_exist[b * QQ + q_];
            acc += fmaxf(x, 0.0f) + log1pf(expf(-fabsf(x)));
        }
        #pragma unroll
        for (int off = 16; off > 0; off >>= 1) acc += __shfl_down_sync(0xffffffffu, acc, off);
        if (lane == 0) s_bce = acc;
    }
    __syncthreads();

    // ---- Phase 2: pair losses; warp w handles g = 4w..4w+3 ----
    float acc = 0.0f;
    for (int k = 0; k < 4; k++) {
        int g = warp * 4 + k;
        int row = s_match[g];
        const float* pp = pred_pts + (size_t)(b * QQ + row) * PP * 2;
        const float* gp = gt_pts   + (size_t)(b * GG + g) * PP * 2;
        const float* vp = gt_vis   + (size_t)(b * GG + g) * PP;

        float ptsv = 0.0f, viss = 0.0f, smv = 0.0f, cvs = 0.0f;
        #pragma unroll
        for (int h = 0; h < 2; h++) {
            int t = lane + 32 * h;
            float px = pp[2 * t], py = pp[2 * t + 1];
            float gx = gp[2 * t], gy = gp[2 * t + 1];
            float v = vp[t];
            ptsv += (smooth_l1(px - gx) + smooth_l1(py - gy)) * v;
            viss += v;
            if (t >= 1 && t <= PP - 2) {
                float sx = pp[2 * t + 2] - 2.0f * px + pp[2 * t - 2];
                float sy = pp[2 * t + 3] - 2.0f * py + pp[2 * t - 1];
                float mag = sqrtf(fmaxf(sx * sx + sy * sy, 1e-24f));
                float cv = vp[t - 1] * v * vp[t + 1];
                smv += mag * cv;
                cvs += cv;
            }
        }
        #pragma unroll
        for (int off = 16; off > 0; off >>= 1) {
            ptsv += __shfl_down_sync(0xffffffffu, ptsv, off);
            viss += __shfl_down_sync(0xffffffffu, viss, off);
            smv  += __shfl_down_sync(0xffffffffu, smv, off);
            cvs  += __shfl_down_sync(0xffffffffu, cvs, off);
        }
        if (lane == 0) {
            float visS = fmaxf(viss, 1.0f);
            float pts = ptsv / visS;
            float smooth = smv / fmaxf(cvs, 1.0f);
            const float* lg = pred_type + (size_t)(b * QQ + row) * NT;
            int label = gt_type[b * GG + g];
            float mx = lg[0];
            #pragma unroll
            for (int n = 1; n < NT; n++) mx = fmaxf(mx, lg[n]);
            float se = 0.0f;
            #pragma unroll
            for (int n = 0; n < NT; n++) se += expf(lg[n] - mx);
            float ce = mx + logf(se) - lg[label];
            int ci = (b * QQ + row) * GG + g;
            acc += 3.0f * pts + 5.0f * g_curve[ci] + 1.5f * g_dir[ci] +
                   0.25f * smooth + 0.5f * ce;
        }
    }
    if (lane == 0) s_wsum[warp] = acc;
    __syncthreads();

    if (tid == 0) {
        g_blk_pair[b] = s_wsum[0] + s_wsum[1] + s_wsum[2] + s_wsum[3];
        g_blk_x[b] = s_xsum;
        g_blk_bce[b] = s_bce;
        __threadfence();
        int old = atomicAdd(&g_done_counter, 1);
        s_last = (old == BB - 1) ? 1 : 0;
    }
    __syncthreads();
    if (!s_last) return;

    // ---- Phase 3 (last block): combine -> scalar ----
    float pacc = 0.0f, xacc = 0.0f, bacc = 0.0f;
    if (tid < BB) {
        pacc = *((volatile float*)&g_blk_pair[tid]);
        xacc = *((volatile float*)&g_blk_x[tid]);
        bacc = *((volatile float*)&g_blk_bce[tid]);
    }
    s_red[tid] = pacc;
    __syncthreads();
    for (int s = 64; s > 0; s >>= 1) { if (tid < s) s_red[tid] += s_red[tid + s]; __syncthreads(); }
    float pair_sum = s_red[0];
    __syncthreads();
    s_red[tid] = xacc;
    __syncthreads();
    for (int s = 64; s > 0; s >>= 1) { if (tid < s) s_red[tid] += s_red[tid + s]; __syncthreads(); }
    float x_sum = s_red[0];
    __syncthreads();
    s_red[tid] = bacc;
    __syncthreads();
    for (int s = 64; s > 0; s >>= 1) { if (tid < s) s_red[tid] += s_red[tid + s]; __syncthreads(); }
    if (tid == 0) {
        float bce_sum = s_red[0];
        float bce = (bce_sum - x_sum) * (1.0f / (BB * QQ));
        out[0] = 1.5f * bce + pair_sum * (1.0f / (BB * GG));
        g_done_counter = 0;
    }
}

// ---------------------------------------------------------------------------
extern "C" void kernel_launch(void* const* d_in, const int* in_sizes, int n_in,
                              void* d_out, int out_size)
{
    const float* pred_exist = (const float*)d_in[0];
    const float* pred_pts   = (const float*)d_in[1];
    const float* pred_type  = (const float*)d_in[2];
    const float* gt_points  = (const float*)d_in[4];
    const float* gt_vis     = (const float*)d_in[5];
    const int*   gt_type    = (const int*)d_in[6];
    float* out = (float*)d_out;

    cost_kernel<<<BB * QQ * GG, PP>>>(pred_pts, gt_points, gt_vis, pred_exist);
    hungarian_pair_final_kernel<<<BB, 128>>>(pred_exist, pred_pts, pred_type,
                                             gt_points, gt_vis, gt_type, out);
}

// round 16
// speedup vs baseline: 1.1788x; 1.1788x over previous
#include <cuda_runtime.h>
#include <cuda_bf16.h>
#include <math.h>

#define BB 16
#define QQ 50
#define GG 16
#define PP 64
#define NT 7
#define NSEG (PP - 1)

typedef unsigned long long u64;

// packed f32x2 helpers (only fma/mul/add exist for f32x2 on this toolchain)
#define F2PACK(d, lo, hi)  asm("mov.b64 %0, {%1,%2};" : "=l"(d) : "f"(lo), "f"(hi))
#define F2UNPACK(lo, hi, s) asm("mov.b64 {%0,%1}, %2;" : "=f"(lo), "=f"(hi) : "l"(s))
#define F2FMA(d, a, b, c)  asm("fma.rn.f32x2 %0, %1, %2, %3;" : "=l"(d) : "l"(a), "l"(b), "l"(c))
#define F2MUL(d, a, b)     asm("mul.rn.f32x2 %0, %1, %2;" : "=l"(d) : "l"(a), "l"(b))

// Scratch (device globals; no allocation allowed)
__device__ float g_curve[BB * QQ * GG];
__device__ float g_dir[BB * QQ * GG];
__device__ float g_cost[BB * QQ * GG];
__device__ float g_blk_pair[BB];
__device__ float g_blk_x[BB];
__device__ float g_blk_bce[BB];
__device__ int   g_done_counter;   // zero-init; last block resets each run

// ---------------------------------------------------------------------------
// Kernel A (R12-proven, frozen): cost matrix. One block per (b,q,g), 64 thr.
// Each WARP covers all 64 points (lane owns pts lane & lane+32); warps split
// the segment range (w0: 0-31, w1: 31-62 dynamic bounds). Packed f32x2 math.
// ---------------------------------------------------------------------------
__global__ __launch_bounds__(PP) void cost_kernel(
    const float* __restrict__ pred_pts,
    const float* __restrict__ gt_pts,
    const float* __restrict__ gt_vis,
    const float* __restrict__ pred_exist)
{
    int blk = blockIdx.x;
    int g = blk % GG;
    int q = (blk / GG) % QQ;
    int b = blk / (GG * QQ);
    int t = threadIdx.x;   // 0..63
    int lane = t & 31, wid = t >> 5;

    __shared__ float2 sP[PP], sG[PP];
    __shared__ float  sV[PP];
    __shared__ ulonglong2 sS0[NSEG];  // (nx2, ny2)
    __shared__ ulonglong2 sS1[NSEG];  // (cr2, bx2)
    __shared__ ulonglong2 sS2[NSEG];  // (by2, cpa2)
    __shared__ u64        sS3[NSEG];  // ab22
    __shared__ float  sTdot[NSEG];
    __shared__ float  sMLo[2][PP], sMHi[2][PP];
    __shared__ float  sred[5][2];

    const float2* pp = (const float2*)(pred_pts + ((size_t)(b * QQ + q)) * PP * 2);
    const float2* gp = (const float2*)(gt_pts   + ((size_t)(b * GG + g)) * PP * 2);
    sP[t] = pp[t];
    sG[t] = gp[t];
    sV[t] = gt_vis[(size_t)(b * GG + g) * PP + t];
    __syncthreads();

    if (t < NSEG) {
        float2 aG = sG[t], bG = sG[t + 1];
        float abxg = bG.x - aG.x, abyg = bG.y - aG.y;
        float ab2g = abxg * abxg + abyg * abyg;
        float invg = 1.0f / fmaxf(ab2g, 1e-8f);
        float nxg = abxg * invg, nyg = abyg * invg;
        float crg = -(aG.x * abxg + aG.y * abyg) * invg;

        float2 aP = sP[t], bP = sP[t + 1];
        float abxp = bP.x - aP.x, abyp = bP.y - aP.y;
        float ab2p = abxp * abxp + abyp * abyp;
        float invp = 1.0f / fmaxf(ab2p, 1e-8f);
        float nxp = abxp * invp, nyp = abyp * invp;
        float crp = -(aP.x * abxp + aP.y * abyp) * invp;

        u64 nx2, ny2, cr2, bx2, by2, cpa2, ab22;
        F2PACK(nx2, nxg, nxp);
        F2PACK(ny2, nyg, nyp);
        F2PACK(cr2, crg, crp);
        F2PACK(bx2, -2.0f * aG.x, -2.0f * aP.x);
        F2PACK(by2, -2.0f * aG.y, -2.0f * aP.y);
        F2PACK(cpa2, aG.x * aG.x + aG.y * aG.y, aP.x * aP.x + aP.y * aP.y);
        F2PACK(ab22, ab2g, ab2p);
        sS0[t] = make_ulonglong2(nx2, ny2);
        sS1[t] = make_ulonglong2(cr2, bx2);
        sS2[t] = make_ulonglong2(by2, cpa2);
        sS3[t] = ab22;

        float itg = 1.0f / fmaxf(sqrtf(ab2g), 1e-6f);
        float itp = 1.0f / fmaxf(sqrtf(ab2p), 1e-6f);
        sTdot[t] = (abxp * abxg + abyp * abyg) * itg * itp;
    }
    __syncthreads();

    float2 Pa = sP[lane],      Ga = sG[lane];
    float2 Pb = sP[lane + 32], Gb = sG[lane + 32];
    u64 PxA, PyA, PxB, PyB, NEG2;
    F2PACK(PxA, Pa.x, Ga.x);
    F2PACK(PyA, Pa.y, Ga.y);
    F2PACK(PxB, Pb.x, Gb.x);
    F2PACK(PyB, Pb.y, Gb.y);
    F2PACK(NEG2, -2.0f, -2.0f);

    float mLoA = 3.0e38f, mHiA = 3.0e38f, mLoB = 3.0e38f, mHiB = 3.0e38f;
    int jBeg = wid ? 32 : 0;
    int jEnd = wid ? 63 : 32;

    #pragma unroll 4
    for (int j = jBeg; j < jEnd; j++) {
        ulonglong2 A = sS0[j];
        ulonglong2 Bv = sS1[j];
        ulonglong2 Cv = sS2[j];
        u64 ab22 = sS3[j];

        {   // point slot A (pt = lane)
            u64 r2, pa2, t2, w2, z2, val2;
            F2FMA(r2, PyA, A.y, Bv.x);
            F2FMA(r2, PxA, A.x, r2);
            F2FMA(pa2, PyA, Cv.x, Cv.y);
            F2FMA(pa2, PxA, Bv.y, pa2);
            float rl, rh;
            F2UNPACK(rl, rh, r2);
            float tl = __saturatef(rl), th = __saturatef(rh);
            F2PACK(t2, tl, th);
            F2FMA(w2, r2, NEG2, t2);     // t - 2r
            F2MUL(z2, t2, w2);
            F2FMA(val2, z2, ab22, pa2);
            float vl, vh;
            F2UNPACK(vl, vh, val2);
            mLoA = fminf(mLoA, vl);
            mHiA = fminf(mHiA, vh);
        }
        {   // point slot B (pt = lane+32)
            u64 r2, pa2, t2, w2, z2, val2;
            F2FMA(r2, PyB, A.y, Bv.x);
            F2FMA(r2, PxB, A.x, r2);
            F2FMA(pa2, PyB, Cv.x, Cv.y);
            F2FMA(pa2, PxB, Bv.y, pa2);
            float rl, rh;
            F2UNPACK(rl, rh, r2);
            float tl = __saturatef(rl), th = __saturatef(rh);
            F2PACK(t2, tl, th);
            F2FMA(w2, r2, NEG2, t2);
            F2MUL(z2, t2, w2);
            F2FMA(val2, z2, ab22, pa2);
            float vl, vh;
            F2UNPACK(vl, vh, val2);
            mLoB = fminf(mLoB, vl);
            mHiB = fminf(mHiB, vh);
        }
    }
    sMLo[wid][lane] = mLoA; sMLo[wid][lane + 32] = mLoB;
    sMHi[wid][lane] = mHiA; sMHi[wid][lane + 32] = mHiB;
    __syncthreads();

    float mLo = fminf(sMLo[0][t], sMLo[1][t]);
    float mHi = fminf(sMHi[0][t], sMHi[1][t]);
    float2 myP = sP[t];
    float2 myG = sG[t];
    float myV = sV[t];

    float pp2 = myP.x * myP.x + myP.y * myP.y;
    float gg2 = myG.x * myG.x + myG.y * myG.y;
    float v0 = sqrtf(fmaxf(mLo + pp2, 1e-24f));          // dp2g
    float v1 = sqrtf(fmaxf(mHi + gg2, 1e-24f)) * myV;    // dg2p * vis
    float v2 = myV;
    float v3 = 0.0f, v4 = 0.0f;
    if (t < NSEG) {
        float sv_ = myV * sV[t + 1];
        v3 = (1.0f - sTdot[t]) * sv_;
        v4 = sv_;
    }

    #pragma unroll
    for (int off = 16; off > 0; off >>= 1) {
        v0 += __shfl_down_sync(0xffffffffu, v0, off);
        v1 += __shfl_down_sync(0xffffffffu, v1, off);
        v2 += __shfl_down_sync(0xffffffffu, v2, off);
        v3 += __shfl_down_sync(0xffffffffu, v3, off);
        v4 += __shfl_down_sync(0xffffffffu, v4, off);
    }
    if (lane == 0) {
        sred[0][wid] = v0; sred[1][wid] = v1; sred[2][wid] = v2;
        sred[3][wid] = v3; sred[4][wid] = v4;
    }
    __syncthreads();
    if (t == 0) {
        float s0 = sred[0][0] + sred[0][1];
        float s1 = sred[1][0] + sred[1][1];
        float s2 = sred[2][0] + sred[2][1];
        float s3 = sred[3][0] + sred[3][1];
        float s4 = sred[4][0] + sred[4][1];
        float visS = fmaxf(s2, 1.0f);
        float curve = 0.5f * (s0 * (1.0f / PP) + s1 / visS);
        float dir = s3 / fmaxf(s4, 1.0f);
        int idx = (b * QQ + q) * GG + g;
        g_curve[idx] = curve;
        g_dir[idx] = dir;
        float x = pred_exist[b * QQ + q];
        float sig = 1.0f / (1.0f + expf(-x));
        g_cost[idx] = curve + 0.35f * dir - 0.25f * sig;
    }
}

// ---------------------------------------------------------------------------
// Kernel B: ARR (R12-proven) + BRANCH-FREE Dijkstra step body:
// sway registerized (way0/way1, select-updated, stored once post-loop);
// lane-ownership and have1 gating via boolean selects (no BSSY regions).
// ---------------------------------------------------------------------------
__device__ __forceinline__ unsigned okey(float f) {
    unsigned u = __float_as_uint(f);
    return (u & 0x80000000u) ? ~u : (u | 0x80000000u);
}
__device__ __forceinline__ float deokey(unsigned k) {
    unsigned u = (k & 0x80000000u) ? (k & 0x7FFFFFFFu) : ~k;
    return __uint_as_float(u);
}
__device__ __forceinline__ float smooth_l1(float x) {
    float ax = fabsf(x);
    return (ax < 1.0f) ? 0.5f * x * x : ax - 0.5f;
}

__global__ __launch_bounds__(128) void hungarian_pair_final_kernel(
    const float* __restrict__ pred_exist,
    const float* __restrict__ pred_pts,
    const float* __restrict__ pred_type,
    const float* __restrict__ gt_pts,
    const float* __restrict__ gt_vis,
    const int*   __restrict__ gt_type,
    float* __restrict__ out)
{
    int b = blockIdx.x;
    int tid = threadIdx.x;
    int lane = tid & 31, warp = tid >> 5;

    __shared__ float sC[GG][QQ];
    __shared__ int   sRow[QQ];
    __shared__ int   sway[QQ];
    __shared__ int   s_match[GG];
    __shared__ float s_wsum[4];
    __shared__ float s_xsum, s_bce;
    __shared__ int   s_last;
    __shared__ float s_red[128];

    for (int idx = tid; idx < GG * QQ; idx += 128) {
        int qq = idx >> 4, gg = idx & 15;
        sC[gg][qq] = g_cost[(b * QQ + qq) * GG + gg];
    }
    if (tid < QQ) sRow[tid] = -1;
    __syncthreads();

    if (warp == 0) {
        const float INF_F = 1e30f;
        int c0 = lane, c1 = lane + 32;
        bool have1 = (c1 < QQ);
        int c1r = have1 ? c1 : 0;     // clamped for safe (discarded) loads
        float v0 = 0.0f, v1 = 0.0f;   // column potentials, stay <= 0

        // ---- Augmenting Row Reduction (R12-proven: exact duals) ----
        unsigned todo = (1u << GG) - 1u;
        int steps = 0;
        while (todo && steps < 64) {
            steps++;
            int i = __ffs(todo) - 1;
            float a0 = sC[i][c0] - v0;
            float a1 = have1 ? (sC[i][c1r] - v1) : INF_F;
            bool pick1 = a1 < a0;
            float lo = pick1 ? a1 : a0;
            float hi = pick1 ? a0 : a1;
            int locol = pick1 ? c1 : c0;
            unsigned klo = okey(lo);
            unsigned kmin = __reduce_min_sync(0xffffffffu, klo);   // exact min
            unsigned ball = __ballot_sync(0xffffffffu, klo == kmin);
            int jl = __ffs(ball) - 1;                              // winner lane
            int j1 = __shfl_sync(0xffffffffu, locol, jl);
            float m1 = deokey(kmin);                               // exact
            float lo2 = (lane == jl) ? hi : lo;
            float m2 = deokey(__reduce_min_sync(0xffffffffu, okey(lo2)));
            float dv = m2 - m1;                                    // >= 0 exact
            int kprev = sRow[j1];                                  // broadcast read
            __syncwarp();
            if (lane == jl) {
                if (j1 < 32) v0 -= dv; else v1 -= dv;
                sRow[j1] = i;
            }
            todo &= ~(1u << i);
            if (kprev >= 0) todo |= (1u << kprev);
            __syncwarp();
        }

        // ---- Exact Dijkstra with branch-free step body ----
        unsigned pending = todo;
        while (pending) {
            int r0 = __ffs(pending) - 1;
            pending &= pending - 1;

            int rc0 = sRow[c0];
            int rc1 = have1 ? sRow[c1r] : -1;
            float w0 = (rc0 >= 0) ? (sC[rc0][c0] - v0) : 0.0f;
            float w1 = (rc1 >= 0) ? (sC[rc1][c1r] - v1) : 0.0f;
            float d0 = sC[r0][c0] - v0;
            float d1 = have1 ? (sC[r0][c1r] - v1) : INF_F;
            int way0 = -1, way1 = -1;   // registerized sway
            bool sc0 = false, sc1 = false;
            int jf; float D;

            while (true) {
                float cand0 = sc0 ? INF_F : d0;
                float cand1 = sc1 ? INF_F : d1;
                bool pick1 = cand1 < cand0;
                float bval = pick1 ? cand1 : cand0;
                unsigned bcol = pick1 ? (unsigned)c1 : (unsigned)c0;
                unsigned key = (okey(bval) & 0xFFFFFFC0u) | bcol;
                unsigned kmin = __reduce_min_sync(0xffffffffu, key);
                int js = (int)(kmin & 63u);
                int jl = js & 31;
                bool hiSlot = js >= 32;
                float sendD = hiSlot ? d1 : d0;
                float sendW = hiSlot ? w1 : w0;
                int   sendR = hiSlot ? rc1 : rc0;
                D         = __shfl_sync(0xffffffffu, sendD, jl);
                float Wjs = __shfl_sync(0xffffffffu, sendW, jl);
                int   rws = __shfl_sync(0xffffffffu, sendR, jl);
                bool me = (lane == jl);
                sc0 = sc0 || (me && !hiSlot);     // select, no branch
                sc1 = sc1 || (me && hiSlot);
                if (rws < 0) { jf = js; break; }
                float h = Wjs - D;
                float a0 = sC[rws][c0] - v0 - h;
                bool u0 = !sc0 && (a0 < d0);
                d0   = u0 ? a0 : d0;
                way0 = u0 ? js : way0;
                float a1 = sC[rws][c1r] - v1 - h;
                bool u1 = have1 && !sc1 && (a1 < d1);
                d1   = u1 ? a1 : d1;
                way1 = u1 ? js : way1;
            }
            if (sc0) v0 += d0 - D;
            if (sc1) v1 += d1 - D;
            sway[c0] = way0;                      // single post-loop store
            if (have1) sway[c1] = way1;
            __syncwarp();
            if (lane == 0) {
                int cur = jf;
                while (true) {
                    int src = sway[cur];
                    if (src < 0) { sRow[cur] = r0; break; }
                    sRow[cur] = sRow[src];
                    cur = src;
                }
            }
            __syncwarp();
        }
        // extract matches
        {
            int r = sRow[c0];
            if (r >= 0) s_match[r] = c0;
            if (have1) { int r2 = sRow[c1]; if (r2 >= 0) s_match[r2] = c1; }
        }
        __syncwarp();
        float xs = (lane < GG) ? pred_exist[b * QQ + s_match[lane]] : 0.0f;
        #pragma unroll
        for (int off = 16; off > 0; off >>= 1) xs += __shfl_down_sync(0xffffffffu, xs, off);
        if (lane == 0) s_xsum = xs;
    } else if (warp == 1) {
        float acc = 0.0f;
        for (int q_ = lane; q_ < QQ; q_ += 32) {
            float x = pred_exist[b * QQ + q_];
            acc += fmaxf(x, 0.0f) + log1pf(expf(-fabsf(x)));
        }
        #pragma unroll
        for (int off = 16; off > 0; off >>= 1) acc += __shfl_down_sync(0xffffffffu, acc, off);
        if (lane == 0) s_bce = acc;
    }
    __syncthreads();

    // ---- Phase 2: pair losses; warp w handles g = 4w..4w+3 ----
    float acc = 0.0f;
    for (int k = 0; k < 4; k++) {
        int g = warp * 4 + k;
        int row = s_match[g];
        const float* pp = pred_pts + (size_t)(b * QQ + row) * PP * 2;
        const float* gp = gt_pts   + (size_t)(b * GG + g) * PP * 2;
        const float* vp = gt_vis   + (size_t)(b * GG + g) * PP;

        float ptsv = 0.0f, viss = 0.0f, smv = 0.0f, cvs = 0.0f;
        #pragma unroll
        for (int h = 0; h < 2; h++) {
            int t = lane + 32 * h;
            float px = pp[2 * t], py = pp[2 * t + 1];
            float gx = gp[2 * t], gy = gp[2 * t + 1];
            float v = vp[t];
            ptsv += (smooth_l1(px - gx) + smooth_l1(py - gy)) * v;
            viss += v;
            if (t >= 1 && t <= PP - 2) {
                float sx = pp[2 * t + 2] - 2.0f * px + pp[2 * t - 2];
                float sy = pp[2 * t + 3] - 2.0f * py + pp[2 * t - 1];
                float mag = sqrtf(fmaxf(sx * sx + sy * sy, 1e-24f));
                float cv = vp[t - 1] * v * vp[t + 1];
                smv += mag * cv;
                cvs += cv;
            }
        }
        #pragma unroll
        for (int off = 16; off > 0; off >>= 1) {
            ptsv += __shfl_down_sync(0xffffffffu, ptsv, off);
            viss += __shfl_down_sync(0xffffffffu, viss, off);
            smv  += __shfl_down_sync(0xffffffffu, smv, off);
            cvs  += __shfl_down_sync(0xffffffffu, cvs, off);
        }
        if (lane == 0) {
            float visS = fmaxf(viss, 1.0f);
            float pts = ptsv / visS;
            float smooth = smv / fmaxf(cvs, 1.0f);
            const float* lg = pred_type + (size_t)(b * QQ + row) * NT;
            int label = gt_type[b * GG + g];
            float mx = lg[0];
            #pragma unroll
            for (int n = 1; n < NT; n++) mx = fmaxf(mx, lg[n]);
            float se = 0.0f;
            #pragma unroll
            for (int n = 0; n < NT; n++) se += expf(lg[n] - mx);
            float ce = mx + logf(se) - lg[label];
            int ci = (b * QQ + row) * GG + g;
            acc += 3.0f * pts + 5.0f * g_curve[ci] + 1.5f * g_dir[ci] +
                   0.25f * smooth + 0.5f * ce;
        }
    }
    if (lane == 0) s_wsum[warp] = acc;
    __syncthreads();

    if (tid == 0) {
        g_blk_pair[b] = s_wsum[0] + s_wsum[1] + s_wsum[2] + s_wsum[3];
        g_blk_x[b] = s_xsum;
        g_blk_bce[b] = s_bce;
        __threadfence();
        int old = atomicAdd(&g_done_counter, 1);
        s_last = (old == BB - 1) ? 1 : 0;
    }
    __syncthreads();
    if (!s_last) return;

    // ---- Phase 3 (last block): combine -> scalar ----
    float pacc = 0.0f, xacc = 0.0f, bacc = 0.0f;
    if (tid < BB) {
        pacc = *((volatile float*)&g_blk_pair[tid]);
        xacc = *((volatile float*)&g_blk_x[tid]);
        bacc = *((volatile float*)&g_blk_bce[tid]);
    }
    s_red[tid] = pacc;
    __syncthreads();
    for (int s = 64; s > 0; s >>= 1) { if (tid < s) s_red[tid] += s_red[tid + s]; __syncthreads(); }
    float pair_sum = s_red[0];
    __syncthreads();
    s_red[tid] = xacc;
    __syncthreads();
    for (int s = 64; s > 0; s >>= 1) { if (tid < s) s_red[tid] += s_red[tid + s]; __syncthreads(); }
    float x_sum = s_red[0];
    __syncthreads();
    s_red[tid] = bacc;
    __syncthreads();
    for (int s = 64; s > 0; s >>= 1) { if (tid < s) s_red[tid] += s_red[tid + s]; __syncthreads(); }
    if (tid == 0) {
        float bce_sum = s_red[0];
        float bce = (bce_sum - x_sum) * (1.0f / (BB * QQ));
        out[0] = 1.5f * bce + pair_sum * (1.0f / (BB * GG));
        g_done_counter = 0;
    }
}

// ---------------------------------------------------------------------------
extern "C" void kernel_launch(void* const* d_in, const int* in_sizes, int n_in,
                              void* d_out, int out_size)
{
    const float* pred_exist = (const float*)d_in[0];
    const float* pred_pts   = (const float*)d_in[1];
    const float* pred_type  = (const float*)d_in[2];
    const float* gt_points  = (const float*)d_in[4];
    const float* gt_vis     = (const float*)d_in[5];
    const int*   gt_type    = (const int*)d_in[6];
    float* out = (float*)d_out;

    cost_kernel<<<BB * QQ * GG, PP>>>(pred_pts, gt_points, gt_vis, pred_exist);
    hungarian_pair_final_kernel<<<BB, 128>>>(pred_exist, pred_pts, pred_type,
                                             gt_points, gt_vis, gt_type, out);
}